// round 8
// baseline (speedup 1.0000x reference)
#include <cuda_runtime.h>
#include <cuda_bf16.h>
#include <cstdint>
#include <cstddef>

#define VSZ 32000
#define TT 64
#define BB 32
#define HH 32
#define EE 200
#define NT (BB*TT)            // 2048 tasks
#define BM 64                 // tasks per block (4 m-warps x 16)
#define BN 128                // vocab per block (2 n-warps x 64)
#define NCHB (VSZ/BN)         // 250 blocks in N
#define NCH2 (VSZ/64)         // 500 partial chunks (n64 granularity)
#define ASTRIDE 144           // smem row stride bytes (128B data + 16B pad, LDSM conflict-free)
#define LOG2E 1.4426950408889634f
#define EPS_ARG 0.01f

// ---------------- scratch ----------------
__device__ float g_xproj[NT*HH];
__device__ float g_H[NT*HH];
__device__ uint4 g_Hs[NT*8];      // [task][64 bf16]: k0-31 hi, k0-31 lo
__device__ uint4 g_Ws[VSZ*8];     // [v][64 bf16]:    k0-31 hi, k0-31 lo
__device__ float g_Spart[NCH2*NT];
__device__ float g_C[NT];
__device__ float g_Mpart[NCH2*NT];

// ---------------- helpers ----------------
__device__ __forceinline__ float ex2a(float x){
    float r; asm("ex2.approx.f32 %0, %1;" : "=f"(r) : "f"(x)); return r;
}
__device__ __forceinline__ float tanh_acc(float x){
    float t = expf(2.0f * x);
    return (t - 1.0f) / (t + 1.0f);
}
__device__ __forceinline__ void ldsm4(uint32_t* r, uint32_t addr){
    asm volatile("ldmatrix.sync.aligned.m8n8.x4.shared.b16 {%0,%1,%2,%3}, [%4];"
        : "=r"(r[0]), "=r"(r[1]), "=r"(r[2]), "=r"(r[3]) : "r"(addr));
}
__device__ __forceinline__ void mma16816(float* c, const uint32_t* a, const uint32_t* b){
    asm volatile("mma.sync.aligned.m16n8k16.row.col.f32.bf16.bf16.f32 "
        "{%0,%1,%2,%3}, {%4,%5,%6,%7}, {%8,%9}, {%0,%1,%2,%3};"
        : "+f"(c[0]), "+f"(c[1]), "+f"(c[2]), "+f"(c[3])
        : "r"(a[0]), "r"(a[1]), "r"(a[2]), "r"(a[3]), "r"(b[0]), "r"(b[1]));
}

// ---------------- K1: xproj ----------------
__global__ void k_xproj(const int* __restrict__ y, const float* __restrict__ emb,
                        const float* __restrict__ Wi, const float* __restrict__ bi,
                        const float* __restrict__ bh){
    int task = blockIdx.x * 8 + (threadIdx.x >> 5);
    int j = threadIdx.x & 31;
    int yv = y[task];
    const float4* er = (const float4*)(emb + (size_t)yv * EE);
    const float4* wr = (const float4*)(Wi + (size_t)j * EE);
    float a0 = 0.f, a1 = 0.f, a2 = 0.f, a3 = 0.f;
#pragma unroll 10
    for (int i = 0; i < EE/4; i++){
        float4 e = er[i]; float4 w = wr[i];
        a0 += e.x * w.x; a1 += e.y * w.y; a2 += e.z * w.z; a3 += e.w * w.w;
    }
    g_xproj[task*HH + j] = (a0 + a1) + (a2 + a3) + bi[j] + bh[j];
}

// ---------------- K2: recurrence ----------------
__global__ void k_hchain(const float* __restrict__ enc, const float* __restrict__ Wh){
    int b = blockIdx.x;
    int j = threadIdx.x;
    float wh[HH];
#pragma unroll
    for (int k = 0; k < HH; k++) wh[k] = Wh[j*HH + k];
    __shared__ float hs[HH];
    hs[j] = enc[b*HH + j];
    __syncwarp();
    for (int t = 0; t < TT; t++){
        int row = b*TT + t;
        float a0 = g_xproj[row*HH + j], a1 = 0.f, a2 = 0.f, a3 = 0.f;
#pragma unroll
        for (int k = 0; k < HH; k += 4){
            a0 += wh[k]   * hs[k];
            a1 += wh[k+1] * hs[k+1];
            a2 += wh[k+2] * hs[k+2];
            a3 += wh[k+3] * hs[k+3];
        }
        float h = tanh_acc((a0 + a1) + (a2 + a3));
        __syncwarp();
        hs[j] = h;
        g_H[row*HH + j] = h;
        __syncwarp();
    }
}

// ---------------- bf16 hi/lo splits ----------------
__global__ void k_splitH(){
    int i = blockIdx.x*256 + threadIdx.x;            // NT*HH
    float w = g_H[i];
    int row = i >> 5, col = i & 31;
    __nv_bfloat16 hi = __float2bfloat16(w);
    __nv_bfloat16 lo = __float2bfloat16(w - __bfloat162float(hi));
    __nv_bfloat16* p = (__nv_bfloat16*)g_Hs;
    p[row*64 + col] = hi;
    p[row*64 + 32 + col] = lo;
}
__global__ void k_splitW(const float* __restrict__ Wo){
    int i = blockIdx.x*256 + threadIdx.x;            // VSZ*HH
    float w = Wo[i];
    int row = i >> 5, col = i & 31;
    __nv_bfloat16 hi = __float2bfloat16(w);
    __nv_bfloat16 lo = __float2bfloat16(w - __bfloat162float(hi));
    __nv_bfloat16* p = (__nv_bfloat16*)g_Ws;
    p[row*64 + col] = hi;
    p[row*64 + 32 + col] = lo;
}

// ---------------- HMMA GEMM (PASS 1: expsum+max partials; PASS 2: write logp) ----------------
template<int PASS>
__global__ void __launch_bounds__(256) k_mma(const float* __restrict__ bo,
                                             float* __restrict__ out){
    __shared__ __align__(16) char sA[BM*ASTRIDE];    // 9216 B
    __shared__ __align__(16) char sB[BN*ASTRIDE];    // 18432 B
    __shared__ float sbo[BN];
    int tid = threadIdx.x, wid = tid >> 5, lane = tid & 31;
    int mi = wid >> 1, ni = wid & 1;
    int task0 = blockIdx.x * BM;
    int vb = blockIdx.y * BN;

    // stage A (64 tasks x 128B) and B (128 v x 128B), 144B row stride
    {
        const uint4* hsrc = g_Hs + (size_t)task0 * 8;
#pragma unroll
        for (int i = tid; i < BM*8; i += 256)
            *(uint4*)(sA + (i >> 3)*ASTRIDE + (i & 7)*16) = hsrc[i];
        const uint4* wsrc = g_Ws + (size_t)vb * 8;
#pragma unroll
        for (int i = tid; i < BN*8; i += 256)
            *(uint4*)(sB + (i >> 3)*ASTRIDE + (i & 7)*16) = wsrc[i];
        for (int i = tid; i < BN; i += 256) sbo[i] = bo[vb + i];
    }
    __syncthreads();

    uint32_t uA = (uint32_t)__cvta_generic_to_shared(sA);
    uint32_t uB = (uint32_t)__cvta_generic_to_shared(sB);

    // A fragments: m16 rows of this m-warp, hi (k0-31) + lo (k0-31)
    uint32_t aaddr = uA + (mi*16 + (lane & 15))*ASTRIDE + (lane >> 4)*16;
    uint32_t ah0[4], ah1[4], al0[4], al1[4];
    ldsm4(ah0, aaddr);        // hi k0-15
    ldsm4(ah1, aaddr + 32);   // hi k16-31
    ldsm4(al0, aaddr + 64);   // lo k0-15
    ldsm4(al1, aaddr + 96);   // lo k16-31

    int r4 = lane >> 2, q4 = lane & 3;
    int gr = task0 + mi*16 + r4;           // global row (task) for c0/c1; +8 for c2/c3
    float negC0 = 0.f, negC8 = 0.f;
    if (PASS == 2){ negC0 = -g_C[gr]; negC8 = -g_C[gr + 8]; }

    float s_lo = 0.f, s_hi = 0.f, mx_lo = -3.4e38f, mx_hi = -3.4e38f;

#pragma unroll
    for (int s = 0; s < 8; s++){
        uint32_t baddr = uB + (ni*64 + s*8 + (lane & 7))*ASTRIDE + ((lane >> 3) & 3)*16;
        uint32_t bh[4], bl[4];
        ldsm4(bh, baddr);        // hi k0-31 (pairs: {0,1}=k0-15, {2,3}=k16-31)
        ldsm4(bl, baddr + 64);   // lo k0-31
        float c[4] = {0.f, 0.f, 0.f, 0.f};
        mma16816(c, ah0, bh);        // hi*hi k0
        mma16816(c, ah1, bh + 2);    // hi*hi k1
        mma16816(c, ah0, bl);        // hi*lo k0
        mma16816(c, ah1, bl + 2);    // hi*lo k1
        mma16816(c, al0, bh);        // lo*hi k0
        mma16816(c, al1, bh + 2);    // lo*hi k1

        int colL = ni*64 + s*8 + q4*2;
        float b0 = sbo[colL], b1 = sbo[colL + 1];
        if (PASS == 1){
            float v0 = c[0] + b0, v1 = c[1] + b1;     // row r4
            float v2 = c[2] + b0, v3 = c[3] + b1;     // row r4+8
            s_lo += ex2a(v0*LOG2E) + ex2a(v1*LOG2E);
            s_hi += ex2a(v2*LOG2E) + ex2a(v3*LOG2E);
            mx_lo = fmaxf(mx_lo, fmaxf(v0, v1));
            mx_hi = fmaxf(mx_hi, fmaxf(v2, v3));
        } else {
            float2 o0 = make_float2(c[0] + b0 + negC0, c[1] + b1 + negC0);
            float2 o1 = make_float2(c[2] + b0 + negC8, c[3] + b1 + negC8);
            size_t gcol = (size_t)vb + colL;
            *(float2*)(out + (size_t)gr*VSZ + gcol)       = o0;
            *(float2*)(out + (size_t)(gr+8)*VSZ + gcol)   = o1;
        }
    }
    if (PASS == 1){
        // reduce across the 4 lanes sharing each row (q4 = 0..3)
#pragma unroll
        for (int o = 1; o <= 2; o <<= 1){
            s_lo += __shfl_xor_sync(0xffffffffu, s_lo, o);
            s_hi += __shfl_xor_sync(0xffffffffu, s_hi, o);
            mx_lo = fmaxf(mx_lo, __shfl_xor_sync(0xffffffffu, mx_lo, o));
            mx_hi = fmaxf(mx_hi, __shfl_xor_sync(0xffffffffu, mx_hi, o));
        }
        if (q4 == 0){
            int cy = blockIdx.y*2 + ni;                // n64-granularity chunk id
            g_Spart[(size_t)cy*NT + gr]     = s_lo;
            g_Mpart[(size_t)cy*NT + gr]     = mx_lo;
            g_Spart[(size_t)cy*NT + gr + 8] = s_hi;
            g_Mpart[(size_t)cy*NT + gr + 8] = mx_hi;
        }
    }
}

// ---------------- K4: C[task] = log(sum of 500 partials) ----------------
__global__ void k_lse(){
    __shared__ float ps[4][64];
    int t = threadIdx.x & 63, sl = threadIdx.x >> 6;
    int task = blockIdx.x*64 + t;
    float s = 0.f;
    for (int c = sl; c < NCH2; c += 4) s += g_Spart[(size_t)c*NT + task];
    ps[sl][t] = s;
    __syncthreads();
    if (sl == 0) g_C[task] = logf((ps[0][t] + ps[1][t]) + (ps[2][t] + ps[3][t]));
}

// ---------------- K6: exact-fp32 argmax over tensor-qualified 64-v chunks ----------------
__global__ void __launch_bounds__(256) k_argmax_exact(const float* __restrict__ Wo,
                                                      const float* __restrict__ bo,
                                                      float* __restrict__ preds){
    int wid = threadIdx.x >> 5, lid = threadIdx.x & 31;
    int task = blockIdx.x * 8 + wid;
    float mloc[16];
    float Mt = -3.4e38f;
#pragma unroll
    for (int j = 0; j < 16; j++){
        int c = lid + 32*j;
        float m = (c < NCH2) ? g_Mpart[(size_t)c*NT + task] : -3.4e38f;
        mloc[j] = m;
        if (m > Mt) Mt = m;
    }
#pragma unroll
    for (int o = 16; o; o >>= 1){
        float om = __shfl_xor_sync(0xffffffffu, Mt, o);
        if (om > Mt) Mt = om;
    }
    float thr = Mt - EPS_ARG;   // tensor error << EPS => true-argmax chunk qualifies
    float h[HH];
    {
        const float4* hp = (const float4*)(g_H + (size_t)task * HH);
#pragma unroll
        for (int q = 0; q < 8; q++){
            float4 x = hp[q];
            h[4*q] = x.x; h[4*q+1] = x.y; h[4*q+2] = x.z; h[4*q+3] = x.w;
        }
    }
    float bx = -3.4e38f; int bi_ = 0x7fffffff;
#pragma unroll 1
    for (int j = 0; j < 16; j++){
        int c = lid + 32*j;
        if (c < NCH2 && mloc[j] >= thr){
            int v0 = c * 64;
            for (int v = v0; v < v0 + 64; v++){       // ascending v, strict > => first occurrence
                const float4* wr = (const float4*)(Wo + (size_t)v * HH);
                float a0 = bo[v], a1 = 0.f, a2 = 0.f, a3 = 0.f;
#pragma unroll
                for (int q = 0; q < 8; q++){
                    float4 w = wr[q];
                    a0 += h[4*q]*w.x; a1 += h[4*q+1]*w.y; a2 += h[4*q+2]*w.z; a3 += h[4*q+3]*w.w;
                }
                float d = (a0 + a1) + (a2 + a3);
                if (d > bx){ bx = d; bi_ = v; }
            }
        }
    }
#pragma unroll
    for (int o = 16; o; o >>= 1){
        float om = __shfl_xor_sync(0xffffffffu, bx, o);
        int   oi = __shfl_xor_sync(0xffffffffu, bi_, o);
        if (om > bx || (om == bx && oi < bi_)){ bx = om; bi_ = oi; }  // tie -> min index
    }
    if (lid == 0) preds[task] = (float)bi_;
}

// ---------------- launch ----------------
extern "C" void kernel_launch(void* const* d_in, const int* in_sizes, int n_in,
                              void* d_out, int out_size){
    const int*   y   = (const int*)  d_in[0];
    const float* enc = (const float*)d_in[1];
    const float* emb = (const float*)d_in[2];
    const float* Wi  = (const float*)d_in[3];
    const float* bi  = (const float*)d_in[4];
    const float* Wh  = (const float*)d_in[5];
    const float* bh  = (const float*)d_in[6];
    const float* Wo  = (const float*)d_in[7];
    const float* bo  = (const float*)d_in[8];
    float* out = (float*)d_out;

    k_xproj<<<NT/8, 256>>>(y, emb, Wi, bi, bh);
    k_hchain<<<BB, 32>>>(enc, Wh);
    k_splitH<<<NT*HH/256, 256>>>();
    k_splitW<<<VSZ*HH/256, 256>>>(Wo);
    k_mma<1><<<dim3(NT/BM, NCHB), 256>>>(bo, nullptr);
    k_lse<<<NT/64, 256>>>();
    k_mma<2><<<dim3(NT/BM, NCHB), 256>>>(bo, out);
    if ((long long)out_size > (long long)NT * VSZ){
        k_argmax_exact<<<NT/8, 256>>>(Wo, bo, out + (size_t)NT * VSZ);
    }
}